// round 13
// baseline (speedup 1.0000x reference)
#include <cuda_runtime.h>
#include <cuda_fp16.h>
#include <cstdint>

#define NTOK 65536
#define MT 64
#define MAXTILE 1040

#define SM_X    0
#define SM_B    17408
#define SM_PQ   148480
#define SM_BIAS 183296
#define SM_TOK  185344
#define SMEM_MAIN 185600

__device__ int g_cnt[9];
__device__ int g_ntiles;
__device__ unsigned g_done;
__device__ int g_tok[9 * NTOK];
__device__ int g_te[MAXTILE], g_ts[MAXTILE], g_tn[MAXTILE];
__device__ __align__(16) uint32_t g_Wf[18 * 32768];

__device__ __forceinline__ float tanha(float x) {
    float r; asm volatile("tanh.approx.f32 %0,%1;" : "=f"(r) : "f"(x)); return r;
}
__device__ __forceinline__ float sigf(float v) {
    return fmaf(0.5f, tanha(0.5f * v), 0.5f);
}
__device__ __forceinline__ uint32_t tanh2(uint32_t v) {
    uint32_t r; asm volatile("tanh.approx.f16x2 %0,%1;" : "=r"(r) : "r"(v)); return r;
}
__device__ __forceinline__ __half2 u2h(uint32_t u) { return *(__half2*)&u; }
__device__ __forceinline__ uint32_t h2u(__half2 h) { return *(uint32_t*)&h; }
__device__ __forceinline__ uint32_t sig2(uint32_t v) {
    __half2 hf = __floats2half2_rn(0.5f, 0.5f);
    uint32_t t = tanh2(h2u(__hmul2(u2h(v), hf)));
    return h2u(__hfma2(u2h(t), hf, hf));
}
__device__ __forceinline__ void mma16(float* c, const uint32_t* a, uint32_t b0, uint32_t b1) {
    asm volatile(
        "mma.sync.aligned.m16n8k16.row.col.f32.f16.f16.f32 "
        "{%0,%1,%2,%3},{%4,%5,%6,%7},{%8,%9},{%0,%1,%2,%3};"
        : "+f"(c[0]), "+f"(c[1]), "+f"(c[2]), "+f"(c[3])
        : "r"(a[0]), "r"(a[1]), "r"(a[2]), "r"(a[3]), "r"(b0), "r"(b1));
}
__device__ __forceinline__ uint32_t sptr(const void* p) {
    return (uint32_t)__cvta_generic_to_shared(p);
}
__device__ __forceinline__ void cpa16(uint32_t dst, const void* src) {
    asm volatile("cp.async.cg.shared.global [%0],[%1],16;" :: "r"(dst), "l"(src));
}
__device__ __forceinline__ uint32_t packh2(float a, float b) {
    __half2 h = __floats2half2_rn(a, b);
    return *(uint32_t*)&h;
}
__device__ __forceinline__ uint4 lds128(uint32_t addr) {
    uint4 v;
    asm volatile("ld.shared.v4.b32 {%0,%1,%2,%3},[%4];"
        : "=r"(v.x), "=r"(v.y), "=r"(v.z), "=r"(v.w) : "r"(addr));
    return v;
}
__device__ __forceinline__ void ldsm4(uint32_t* a, uint32_t addr) {
    asm volatile("ldmatrix.sync.aligned.m8n8.x4.shared.b16 {%0,%1,%2,%3},[%4];"
        : "=r"(a[0]), "=r"(a[1]), "=r"(a[2]), "=r"(a[3]) : "r"(addr));
}

__global__ void k_prep_all(const float* __restrict__ W, const int* __restrict__ pos) {
    int b = blockIdx.x;
    int tid = threadIdx.x;
    if (b < 288) {
        __shared__ float s[32 * 128];
        int m = b >> 2, kg = b & 3;
        int l = m / 36, g = (m / 9) % 4, e = m % 9;
        const float* src = W + (size_t)m * 16384 + kg * 4096;
        for (int i = tid; i < 4096; i += 512) s[i] = src[i];
        __syncthreads();
        uint32_t* dst = g_Wf + (size_t)(l * 9 + e) * 32768 + g * 1024;
        for (int i = tid; i < 2048; i += 512) {
            int ksl = i >> 10, nh = (i >> 9) & 1;
            int ntp = (i >> 7) & 3, lane = (i >> 2) & 31, q = i & 3;
            int tig = lane & 3, grp = lane >> 2, bsel = q & 1;
            int n = nh * 64 + (ntp * 2 + (q >> 1)) * 8 + grp;
            int k0l = ksl * 16 + bsel * 8 + 2 * tig;
            dst[(kg * 2 + ksl) * 4096 + nh * 512 + ntp * 128 + lane * 4 + q] =
                packh2(s[k0l * 128 + n], s[(k0l + 1) * 128 + n]);
        }
    } else {
        __shared__ int scnt[9], sbase[9];
        __shared__ int amlast;
        __shared__ int ts[10];
        int t = (b - 288) * 512 + tid;
        if (tid < 9) scnt[tid] = 0;
        int probe = t & 8191;
        int bad = (pos[2 * probe + 1] != 0);
        bad = __syncthreads_or(bad);
        int p = bad ? pos[t] : pos[2 * t];
        int e = p > 8 ? 8 : (p < 0 ? 0 : p);
        int my = atomicAdd(&scnt[e], 1);
        __syncthreads();
        if (tid < 9) sbase[tid] = atomicAdd(&g_cnt[tid], scnt[tid]);
        __syncthreads();
        g_tok[e * NTOK + sbase[e] + my] = t;
        __threadfence();
        __syncthreads();
        if (tid == 0) amlast = ((atomicAdd(&g_done, 1u) & 127u) == 127u);
        __syncthreads();
        if (amlast) {
            if (tid == 0) {
                ts[0] = 0;
                for (int ee = 0; ee < 9; ee++) ts[ee + 1] = ts[ee] + ((g_cnt[ee] + MT - 1) / MT);
                g_ntiles = ts[9];
            }
            __syncthreads();
            int n = ts[9];
            for (int tt = tid; tt < n; tt += 512) {
                int ee = 0;
                while (!(tt >= ts[ee] && tt < ts[ee + 1])) ee++;
                int s = (tt - ts[ee]) * MT;
                g_te[tt] = ee; g_ts[tt] = s;
                int rem = g_cnt[ee] - s;
                g_tn[tt] = rem < MT ? rem : MT;
            }
        }
    }
}

__global__ void __launch_bounds__(1024, 1)
k_main(const float* __restrict__ xin, const float* __restrict__ bs, float* __restrict__ out) {
    extern __shared__ __align__(16) char smc[];
    int bid = blockIdx.x;
    if (bid < g_ntiles) {
    int e = g_te[bid], s0 = g_ts[bid], nr = g_tn[bid];
    int tid = threadIdx.x, lane = tid & 31, w = tid >> 5;
    int g = w >> 3, mh2 = (w >> 2) & 1, nq = w & 3;
    int tig = lane & 3, grp = lane >> 2;

    uint32_t* Xs2 = (uint32_t*)smc;
    uint32_t* Ph = (uint32_t*)(smc + SM_PQ);
    uint32_t* Qh = Ph + 4352;
    uint32_t* sbh = (uint32_t*)(smc + SM_BIAS);
    int* stok = (int*)(smc + SM_TOK);

    if (tid < MT) stok[tid] = (tid < nr) ? g_tok[e * NTOK + s0 + tid] : -1;
    if (tid < 512) {
        int lb = tid >> 8, gb = (tid >> 6) & 3, cpb = tid & 63;
        float2 bv = ((const float2*)(bs + ((lb * 4 + gb) * 9 + e) * 128))[cpb];
        sbh[tid] = packh2(bv.x, bv.y);
    }
    __syncthreads();
    for (int i = tid; i < MT * 32; i += 1024) {
        int r = i >> 5, c4 = i & 31;
        int t = stok[r];
        float4 v = (t >= 0) ? ((const float4*)xin)[(size_t)t * 32 + c4]
                            : make_float4(0.f, 0.f, 0.f, 0.f);
        Xs2[r * 68 + c4 * 2]     = packh2(v.x, v.y);
        Xs2[r * 68 + c4 * 2 + 1] = packh2(v.z, v.w);
    }

    #define STAGE2(lsel) do { \
        const uint4* _w = (const uint4*)(g_Wf + (size_t)((lsel) * 9 + e) * 32768); \
        uint32_t _d = sptr(smc) + SM_B; \
        _Pragma("unroll") \
        for (int _ch = 0; _ch < 2; _ch++) { \
            _Pragma("unroll") \
            for (int _i = 0; _i < 4; _i++) \
                cpa16(_d + _ch * 65536 + (tid + _i * 1024) * 16, \
                      _w + _ch * 4096 + tid + _i * 1024); \
            asm volatile("cp.async.commit_group;"); \
        } \
    } while (0)

    STAGE2(0);

    uint32_t arow = sptr(smc) + (uint32_t)((mh2 * 32 + (lane & 7) + ((lane >> 3) & 1) * 8) * 272
                                           + ((lane >> 4) & 1) * 16);

    for (int l = 0; l < 2; l++) {
        float acc[2][4][4];
        #pragma unroll
        for (int mt = 0; mt < 2; mt++)
            #pragma unroll
            for (int nt = 0; nt < 4; nt++)
                #pragma unroll
                for (int j = 0; j < 4; j++) acc[mt][nt][j] = 0.f;

        #pragma unroll
        for (int ch = 0; ch < 2; ch++) {
            if (ch == 0) asm volatile("cp.async.wait_group 1;");
            else         asm volatile("cp.async.wait_group 0;");
            __syncthreads();
            uint32_t bsb = sptr(smc) + SM_B + ch * 65536 + g * 4096 + (nq >> 1) * 2048
                           + (nq & 1) * 1024 + lane * 16;
            #pragma unroll
            for (int ksq = 0; ksq < 4; ksq++) {
                int ks = ch * 4 + ksq;
                uint32_t a0[4], a1[4];
                ldsm4(a0, arow + ks * 32);
                ldsm4(a1, arow + 16 * 272 + ks * 32);
                #pragma unroll
                for (int ntp = 0; ntp < 2; ntp++) {
                    uint4 b = lds128(bsb + ksq * 16384 + ntp * 512);
                    mma16(acc[0][2 * ntp],     a0, b.x, b.y);
                    mma16(acc[1][2 * ntp],     a1, b.x, b.y);
                    mma16(acc[0][2 * ntp + 1], a0, b.z, b.w);
                    mma16(acc[1][2 * ntp + 1], a1, b.z, b.w);
                }
            }
        }
        __syncthreads();
        if (l == 0) STAGE2(1);

        const uint32_t* sbg = sbh + l * 256 + g * 64;
        #define EPI_LOOP(BODY) \
            _Pragma("unroll") for (int mt = 0; mt < 2; mt++) \
            _Pragma("unroll") for (int nt = 0; nt < 4; nt++) \
            _Pragma("unroll") for (int jh = 0; jh < 2; jh++) { \
                int r = mh2 * 32 + mt * 16 + grp + jh * 8; \
                int cp = nq * 16 + nt * 4 + tig; \
                uint32_t bh = sbg[cp]; \
                uint32_t vh = h2u(__hadd2(u2h(packh2(acc[mt][nt][jh * 2], \
                                                     acc[mt][nt][jh * 2 + 1])), u2h(bh))); \
                (void)r; (void)cp; (void)vh; (void)bh; BODY }

        if (g == 0) {
            EPI_LOOP( Ph[r * 68 + cp] = h2u(__hmul2(u2h(Xs2[r * 68 + cp]), u2h(sig2(vh)))); )
        } else if (g == 1) {
            EPI_LOOP( Qh[r * 68 + cp] = tanh2(vh); )
        }
        __syncthreads();
        if (g == 2) {
            EPI_LOOP( Ph[r * 68 + cp] =
                          h2u(__hfma2(u2h(Qh[r * 68 + cp]), u2h(sig2(vh)), u2h(Ph[r * 68 + cp]))); )
        }
        __syncthreads();
        if (g == 3) {
            if (l == 0) {
                EPI_LOOP( Xs2[r * 68 + cp] =
                              h2u(__hmul2(u2h(tanh2(Ph[r * 68 + cp])), u2h(sig2(vh)))); )
            } else {
                EPI_LOOP(
                    __half2 bhh = u2h(bh);
                    float va = acc[mt][nt][jh * 2]     + __low2float(bhh);
                    float vb = acc[mt][nt][jh * 2 + 1] + __high2float(bhh);
                    __half2 phh = u2h(Ph[r * 68 + cp]);
                    int tk = stok[r];
                    if (tk >= 0)
                        ((float2*)out)[(size_t)tk * 64 + cp] =
                            make_float2(tanha(__low2float(phh))  * sigf(va),
                                        tanha(__high2float(phh)) * sigf(vb));
                )
            }
        }
        #undef EPI_LOOP
    }
    #undef STAGE2
    }
    if (blockIdx.x == 0 && threadIdx.x < 9) g_cnt[threadIdx.x] = 0;
}

extern "C" void kernel_launch(void* const* d_in, const int* in_sizes, int n_in,
                              void* d_out, int out_size) {
    const int* pos = (const int*)d_in[0];
    const float* x = (const float*)d_in[1];
    const float* W = (const float*)d_in[2];
    const float* b = (const float*)d_in[3];
    float* out = (float*)d_out;
    (void)in_sizes; (void)n_in; (void)out_size;
    cudaFuncSetAttribute(k_main, cudaFuncAttributeMaxDynamicSharedMemorySize, SMEM_MAIN);
    k_prep_all<<<416, 512>>>(W, pos);
    k_main<<<MAXTILE, 1024, SMEM_MAIN>>>(x, b, out);
}

// round 14
// speedup vs baseline: 1.0362x; 1.0362x over previous
#include <cuda_runtime.h>
#include <cuda_fp16.h>
#include <cstdint>

#define NTOK 65536
#define MT 64
#define MAXTILE 1040

// byte offsets in dynamic smem
#define SM_X    0         // 64*68 half2 words = 17408 B
#define SM_B    17408     // 2 x 65536 B chunk buffers
#define SM_PQ   148480    // Ph: 64x68 half2 (17408 B), Qh follows
#define SM_BIAS 183296    // 1024 floats (both layers)
#define SM_TOK  187392    // 64 ints
#define SMEM_MAIN 187648

__device__ int g_cnt[9];          // zero at start (BSS); re-zeroed at end of k_main
__device__ int g_ntiles;
__device__ unsigned g_done;       // epoch counter (monotonic)
__device__ int g_tok[9 * NTOK];
__device__ int g_te[MAXTILE], g_ts[MAXTILE], g_tn[MAXTILE];
// fragment-ordered fp16 weights: per (l,e): 32768 words
// word = ks*4096 + g*1024 + nh*512 + ntp*128 + lane*4 + q   (ks = 0..7)
__device__ __align__(16) uint32_t g_Wf[18 * 32768];

__device__ __forceinline__ float tanha(float x) {
    float r; asm volatile("tanh.approx.f32 %0,%1;" : "=f"(r) : "f"(x)); return r;
}
__device__ __forceinline__ float sigf(float v) {
    return fmaf(0.5f, tanha(0.5f * v), 0.5f);
}
__device__ __forceinline__ __half2 u2h(uint32_t u) { return *(__half2*)&u; }
__device__ __forceinline__ void mma16(float* c, const uint32_t* a, uint32_t b0, uint32_t b1) {
    asm volatile(
        "mma.sync.aligned.m16n8k16.row.col.f32.f16.f16.f32 "
        "{%0,%1,%2,%3},{%4,%5,%6,%7},{%8,%9},{%0,%1,%2,%3};"
        : "+f"(c[0]), "+f"(c[1]), "+f"(c[2]), "+f"(c[3])
        : "r"(a[0]), "r"(a[1]), "r"(a[2]), "r"(a[3]), "r"(b0), "r"(b1));
}
__device__ __forceinline__ uint32_t sptr(const void* p) {
    return (uint32_t)__cvta_generic_to_shared(p);
}
__device__ __forceinline__ void cpa16(uint32_t dst, const void* src) {
    asm volatile("cp.async.cg.shared.global [%0],[%1],16;" :: "r"(dst), "l"(src));
}
__device__ __forceinline__ uint32_t packh2(float a, float b) {
    __half2 h = __floats2half2_rn(a, b);
    return *(uint32_t*)&h;
}
__device__ __forceinline__ uint4 lds128(uint32_t addr) {
    uint4 v;
    asm volatile("ld.shared.v4.b32 {%0,%1,%2,%3},[%4];"
        : "=r"(v.x), "=r"(v.y), "=r"(v.z), "=r"(v.w) : "r"(addr));
    return v;
}
__device__ __forceinline__ void ldsm4(uint32_t* a, uint32_t addr) {
    asm volatile("ldmatrix.sync.aligned.m8n8.x4.shared.b16 {%0,%1,%2,%3},[%4];"
        : "=r"(a[0]), "=r"(a[1]), "=r"(a[2]), "=r"(a[3]) : "r"(addr));
}

// ---------------- prep: fused wprep (blocks 0..287) + hist/tiles (blocks 288..415) ----
__global__ void k_prep_all(const float* __restrict__ W, const int* __restrict__ pos) {
    int b = blockIdx.x;
    int tid = threadIdx.x;
    if (b < 288) {
        __shared__ float s[32 * 128];
        int m = b >> 2, kg = b & 3;
        int l = m / 36, g = (m / 9) % 4, e = m % 9;
        const float* src = W + (size_t)m * 16384 + kg * 4096;
        for (int i = tid; i < 4096; i += 512) s[i] = src[i];
        __syncthreads();
        uint32_t* dst = g_Wf + (size_t)(l * 9 + e) * 32768 + g * 1024;
        for (int i = tid; i < 2048; i += 512) {
            int ksl = i >> 10, nh = (i >> 9) & 1;
            int ntp = (i >> 7) & 3, lane = (i >> 2) & 31, q = i & 3;
            int tig = lane & 3, grp = lane >> 2, bsel = q & 1;
            int n = nh * 64 + (ntp * 2 + (q >> 1)) * 8 + grp;
            int k0l = ksl * 16 + bsel * 8 + 2 * tig;
            dst[(kg * 2 + ksl) * 4096 + nh * 512 + ntp * 128 + lane * 4 + q] =
                packh2(s[k0l * 128 + n], s[(k0l + 1) * 128 + n]);
        }
    } else {
        __shared__ int scnt[9], sbase[9];
        __shared__ int amlast;
        __shared__ int ts[10];
        int t = (b - 288) * 512 + tid;
        if (tid < 9) scnt[tid] = 0;
        int probe = t & 8191;
        int bad = (pos[2 * probe + 1] != 0);
        bad = __syncthreads_or(bad);
        int p = bad ? pos[t] : pos[2 * t];
        int e = p > 8 ? 8 : (p < 0 ? 0 : p);
        int my = atomicAdd(&scnt[e], 1);
        __syncthreads();
        if (tid < 9) sbase[tid] = atomicAdd(&g_cnt[tid], scnt[tid]);
        __syncthreads();
        g_tok[e * NTOK + sbase[e] + my] = t;
        __threadfence();
        __syncthreads();
        if (tid == 0) amlast = ((atomicAdd(&g_done, 1u) & 127u) == 127u);
        __syncthreads();
        if (amlast) {
            if (tid == 0) {
                ts[0] = 0;
                for (int ee = 0; ee < 9; ee++) ts[ee + 1] = ts[ee] + ((g_cnt[ee] + MT - 1) / MT);
                g_ntiles = ts[9];
            }
            __syncthreads();
            int n = ts[9];
            for (int tt = tid; tt < n; tt += 512) {
                int ee = 0;
                while (!(tt >= ts[ee] && tt < ts[ee + 1])) ee++;
                int s = (tt - ts[ee]) * MT;
                g_te[tt] = ee; g_ts[tt] = s;
                int rem = g_cnt[ee] - s;
                g_tn[tt] = rem < MT ? rem : MT;
            }
        }
    }
}

// ---------------- main: both layers per tile ----------------
// warp = (g in 4, mh2 in 2, nq in 4): m32 x n32 per warp.
__global__ void __launch_bounds__(1024, 1)
k_main(const float* __restrict__ xin, const float* __restrict__ bs, float* __restrict__ out) {
    extern __shared__ __align__(16) char smc[];
    int bid = blockIdx.x;
    if (bid < g_ntiles) {
    int e = g_te[bid], s0 = g_ts[bid], nr = g_tn[bid];
    int tid = threadIdx.x, lane = tid & 31, w = tid >> 5;
    int g = w >> 3, mh2 = (w >> 2) & 1, nq = w & 3;
    int tig = lane & 3, grp = lane >> 2;

    uint32_t* Xs2 = (uint32_t*)smc;               // half2, stride 68 words/row
    uint32_t* Ph = (uint32_t*)(smc + SM_PQ);      // half2 pairs, stride 68
    uint32_t* Qh = Ph + 4352;
    float* sbias = (float*)(smc + SM_BIAS);       // 1024 floats, both layers
    int* stok = (int*)(smc + SM_TOK);

    // stage a layer's 128 KB of weights as two 64 KB cp.async groups
    #define STAGE2(lsel) do { \
        const uint4* _w = (const uint4*)(g_Wf + (size_t)((lsel) * 9 + e) * 32768); \
        uint32_t _d = sptr(smc) + SM_B; \
        _Pragma("unroll") \
        for (int _ch = 0; _ch < 2; _ch++) { \
            _Pragma("unroll") \
            for (int _i = 0; _i < 4; _i++) \
                cpa16(_d + _ch * 65536 + (tid + _i * 1024) * 16, \
                      _w + _ch * 4096 + tid + _i * 1024); \
            asm volatile("cp.async.commit_group;"); \
        } \
    } while (0)

    if (tid < MT) stok[tid] = (tid < nr) ? g_tok[e * NTOK + s0 + tid] : -1;
    sbias[tid] = bs[(((tid >> 9) * 4 + ((tid >> 7) & 3)) * 9 + e) * 128 + (tid & 127)];
    STAGE2(0);                 // B stream in flight while we gather X below
    __syncthreads();
    for (int i = tid; i < MT * 32; i += 1024) {
        int r = i >> 5, c4 = i & 31;
        int t = stok[r];
        float4 v = (t >= 0) ? ((const float4*)xin)[(size_t)t * 32 + c4]
                            : make_float4(0.f, 0.f, 0.f, 0.f);
        Xs2[r * 68 + c4 * 2]     = packh2(v.x, v.y);
        Xs2[r * 68 + c4 * 2 + 1] = packh2(v.z, v.w);
    }

    // ldmatrix base: rows (lane&7)+8*((lane>>3)&1) of this warp's m32 block, col-half (lane>>4)
    uint32_t arow = sptr(smc) + (uint32_t)((mh2 * 32 + (lane & 7) + ((lane >> 3) & 1) * 8) * 272
                                           + ((lane >> 4) & 1) * 16);

    for (int l = 0; l < 2; l++) {
        float acc[2][4][4];
        #pragma unroll
        for (int mt = 0; mt < 2; mt++)
            #pragma unroll
            for (int nt = 0; nt < 4; nt++)
                #pragma unroll
                for (int j = 0; j < 4; j++) acc[mt][nt][j] = 0.f;

        #pragma unroll
        for (int ch = 0; ch < 2; ch++) {
            if (ch == 0) asm volatile("cp.async.wait_group 1;");
            else         asm volatile("cp.async.wait_group 0;");
            __syncthreads();
            uint32_t bsb = sptr(smc) + SM_B + ch * 65536 + g * 4096 + (nq >> 1) * 2048
                           + (nq & 1) * 1024 + lane * 16;
            #pragma unroll
            for (int ksq = 0; ksq < 4; ksq++) {
                int ks = ch * 4 + ksq;
                uint32_t a0[4], a1[4];
                ldsm4(a0, arow + ks * 32);
                ldsm4(a1, arow + 16 * 272 + ks * 32);
                #pragma unroll
                for (int ntp = 0; ntp < 2; ntp++) {
                    uint4 b = lds128(bsb + ksq * 16384 + ntp * 512);
                    mma16(acc[0][2 * ntp],     a0, b.x, b.y);
                    mma16(acc[1][2 * ntp],     a1, b.x, b.y);
                    mma16(acc[0][2 * ntp + 1], a0, b.z, b.w);
                    mma16(acc[1][2 * ntp + 1], a1, b.z, b.w);
                }
            }
        }
        __syncthreads();             // all warps done reading B buffers
        if (l == 0) STAGE2(1);       // overlap layer-1 W staging with epilogue

        const float* sb = sbias + l * 512 + g * 128;

        // σ-hoist: g2/g3 warps fold bias+sigmoid into acc NOW, overlapping phase-1 MUFU.
        if (g >= 2) {
            #pragma unroll
            for (int mt = 0; mt < 2; mt++)
                #pragma unroll
                for (int nt = 0; nt < 4; nt++)
                    #pragma unroll
                    for (int j = 0; j < 4; j++) {
                        int c = 2 * (nq * 16 + nt * 4 + tig) + (j & 1);
                        acc[mt][nt][j] = sigf(acc[mt][nt][j] + sb[c]);
                    }
        }

        #define EPI_LOOP(BODY) \
            _Pragma("unroll") for (int mt = 0; mt < 2; mt++) \
            _Pragma("unroll") for (int nt = 0; nt < 4; nt++) \
            _Pragma("unroll") for (int jh = 0; jh < 2; jh++) { \
                int r = mh2 * 32 + mt * 16 + grp + jh * 8; \
                int cp = nq * 16 + nt * 4 + tig; \
                (void)r; (void)cp; BODY }

        if (g == 0) {
            EPI_LOOP(
                float va = acc[mt][nt][jh * 2]     + sb[2 * cp];
                float vb = acc[mt][nt][jh * 2 + 1] + sb[2 * cp + 1];
                __half2 xh = u2h(Xs2[r * 68 + cp]);
                Ph[r * 68 + cp] = packh2(__low2float(xh) * sigf(va),
                                         __high2float(xh) * sigf(vb));
            )
        } else if (g == 1) {
            EPI_LOOP(
                float va = acc[mt][nt][jh * 2]     + sb[2 * cp];
                float vb = acc[mt][nt][jh * 2 + 1] + sb[2 * cp + 1];
                Qh[r * 68 + cp] = packh2(tanha(va), tanha(vb));
            )
        }
        __syncthreads();
        if (g == 2) {
            EPI_LOOP(
                __half2 qhh = u2h(Qh[r * 68 + cp]);
                __half2 phh = u2h(Ph[r * 68 + cp]);
                float p0 = fmaf(__low2float(qhh),  acc[mt][nt][jh * 2],     __low2float(phh));
                float p1 = fmaf(__high2float(qhh), acc[mt][nt][jh * 2 + 1], __high2float(phh));
                Ph[r * 68 + cp] = packh2(p0, p1);
            )
        }
        __syncthreads();
        if (g == 3) {
            if (l == 0) {
                EPI_LOOP(
                    __half2 phh = u2h(Ph[r * 68 + cp]);
                    Xs2[r * 68 + cp] = packh2(tanha(__low2float(phh))  * acc[mt][nt][jh * 2],
                                              tanha(__high2float(phh)) * acc[mt][nt][jh * 2 + 1]);
                )
            } else {
                EPI_LOOP(
                    __half2 phh = u2h(Ph[r * 68 + cp]);
                    int tk = stok[r];
                    if (tk >= 0)
                        ((float2*)out)[(size_t)tk * 64 + cp] =
                            make_float2(tanha(__low2float(phh))  * acc[mt][nt][jh * 2],
                                        tanha(__high2float(phh)) * acc[mt][nt][jh * 2 + 1]);
                )
            }
        }
        #undef EPI_LOOP
        // no trailing sync needed: next layer's ch0 wait+sync orders Xs2 writes
    }
    #undef STAGE2
    }
    // reset histogram for next launch (graph replay)
    if (blockIdx.x == 0 && threadIdx.x < 9) g_cnt[threadIdx.x] = 0;
}

extern "C" void kernel_launch(void* const* d_in, const int* in_sizes, int n_in,
                              void* d_out, int out_size) {
    const int* pos = (const int*)d_in[0];
    const float* x = (const float*)d_in[1];
    const float* W = (const float*)d_in[2];
    const float* b = (const float*)d_in[3];
    float* out = (float*)d_out;
    (void)in_sizes; (void)n_in; (void)out_size;
    cudaFuncSetAttribute(k_main, cudaFuncAttributeMaxDynamicSharedMemorySize, SMEM_MAIN);
    k_prep_all<<<416, 512>>>(W, pos);
    k_main<<<MAXTILE, 1024, SMEM_MAIN>>>(x, b, out);
}

// round 15
// speedup vs baseline: 1.1139x; 1.0750x over previous
#include <cuda_runtime.h>
#include <cuda_fp16.h>
#include <cstdint>

#define NTOK 65536
#define MT 64
#define MAXTILE 1040

#define SM_X    0
#define SM_B    17408
#define SM_T    148480
#define SM_BIAS 165888
#define SM_TOK  169984
#define SMEM_MAIN 170240

__device__ int g_cnt[9];
__device__ int g_ntiles;
__device__ unsigned g_done;
__device__ int g_tok[9 * NTOK];
__device__ int g_te[MAXTILE], g_ts[MAXTILE], g_tn[MAXTILE];
__device__ __align__(16) uint32_t g_Wf[18 * 32768];

__device__ __forceinline__ float tanha(float x) {
    float r; asm volatile("tanh.approx.f32 %0,%1;" : "=f"(r) : "f"(x)); return r;
}
__device__ __forceinline__ float sigf(float v) {
    return fmaf(0.5f, tanha(0.5f * v), 0.5f);
}
__device__ __forceinline__ __half2 u2h(uint32_t u) { return *(__half2*)&u; }
__device__ __forceinline__ void mma16(float* c, const uint32_t* a, uint32_t b0, uint32_t b1) {
    asm volatile(
        "mma.sync.aligned.m16n8k16.row.col.f32.f16.f16.f32 "
        "{%0,%1,%2,%3},{%4,%5,%6,%7},{%8,%9},{%0,%1,%2,%3};"
        : "+f"(c[0]), "+f"(c[1]), "+f"(c[2]), "+f"(c[3])
        : "r"(a[0]), "r"(a[1]), "r"(a[2]), "r"(a[3]), "r"(b0), "r"(b1));
}
__device__ __forceinline__ uint32_t sptr(const void* p) {
    return (uint32_t)__cvta_generic_to_shared(p);
}
__device__ __forceinline__ void cpa16(uint32_t dst, const void* src) {
    asm volatile("cp.async.cg.shared.global [%0],[%1],16;" :: "r"(dst), "l"(src));
}
__device__ __forceinline__ uint32_t packh2(float a, float b) {
    __half2 h = __floats2half2_rn(a, b);
    return *(uint32_t*)&h;
}
__device__ __forceinline__ uint4 lds128(uint32_t addr) {
    uint4 v;
    asm volatile("ld.shared.v4.b32 {%0,%1,%2,%3},[%4];"
        : "=r"(v.x), "=r"(v.y), "=r"(v.z), "=r"(v.w) : "r"(addr));
    return v;
}
__device__ __forceinline__ void ldsm4(uint32_t* a, uint32_t addr) {
    asm volatile("ldmatrix.sync.aligned.m8n8.x4.shared.b16 {%0,%1,%2,%3},[%4];"
        : "=r"(a[0]), "=r"(a[1]), "=r"(a[2]), "=r"(a[3]) : "r"(addr));
}

__global__ void k_prep_all(const float* __restrict__ W, const int* __restrict__ pos) {
    int b = blockIdx.x;
    int tid = threadIdx.x;
    if (b < 288) {
        __shared__ float s[32 * 128];
        int m = b >> 2, kg = b & 3;
        int l = m / 36, g = (m / 9) % 4, e = m % 9;
        const float* src = W + (size_t)m * 16384 + kg * 4096;
        for (int i = tid; i < 4096; i += 512) s[i] = src[i];
        __syncthreads();
        uint32_t* dst = g_Wf + (size_t)(l * 9 + e) * 32768 + g * 1024;
        for (int i = tid; i < 2048; i += 512) {
            int ksl = i >> 10, nh = (i >> 9) & 1;
            int ntp = (i >> 7) & 3, lane = (i >> 2) & 31, q = i & 3;
            int tig = lane & 3, grp = lane >> 2, bsel = q & 1;
            int n = nh * 64 + (ntp * 2 + (q >> 1)) * 8 + grp;
            int k0l = ksl * 16 + bsel * 8 + 2 * tig;
            dst[(kg * 2 + ksl) * 4096 + nh * 512 + ntp * 128 + lane * 4 + q] =
                packh2(s[k0l * 128 + n], s[(k0l + 1) * 128 + n]);
        }
    } else {
        __shared__ int scnt[9], sbase[9];
        __shared__ int amlast;
        __shared__ int ts[10];
        int t = (b - 288) * 512 + tid;
        if (tid < 9) scnt[tid] = 0;
        int probe = t & 8191;
        int bad = (pos[2 * probe + 1] != 0);
        bad = __syncthreads_or(bad);
        int p = bad ? pos[t] : pos[2 * t];
        int e = p > 8 ? 8 : (p < 0 ? 0 : p);
        int my = atomicAdd(&scnt[e], 1);
        __syncthreads();
        if (tid < 9) sbase[tid] = atomicAdd(&g_cnt[tid], scnt[tid]);
        __syncthreads();
        g_tok[e * NTOK + sbase[e] + my] = t;
        __threadfence();
        __syncthreads();
        if (tid == 0) amlast = ((atomicAdd(&g_done, 1u) & 127u) == 127u);
        __syncthreads();
        if (amlast) {
            if (tid == 0) {
                ts[0] = 0;
                for (int ee = 0; ee < 9; ee++) ts[ee + 1] = ts[ee] + ((g_cnt[ee] + MT - 1) / MT);
                g_ntiles = ts[9];
            }
            __syncthreads();
            int n = ts[9];
            for (int tt = tid; tt < n; tt += 512) {
                int ee = 0;
                while (!(tt >= ts[ee] && tt < ts[ee + 1])) ee++;
                int s = (tt - ts[ee]) * MT;
                g_te[tt] = ee; g_ts[tt] = s;
                int rem = g_cnt[ee] - s;
                g_tn[tt] = rem < MT ? rem : MT;
            }
        }
    }
}

__global__ void __launch_bounds__(1024, 1)
k_main(const float* __restrict__ xin, const float* __restrict__ bs, float* __restrict__ out) {
    extern __shared__ __align__(16) char smc[];
    int bid = blockIdx.x;
    if (bid < g_ntiles) {
    int e = g_te[bid], s0 = g_ts[bid], nr = g_tn[bid];
    int tid = threadIdx.x, lane = tid & 31, w = tid >> 5;
    int gp = w >> 4, mh2 = (w >> 3) & 1, nq = w & 7;
    int tig = lane & 3, grp = lane >> 2;
    int gA = gp ? 1 : 0;
    int dG = gp ? 4096 : 12288;

    uint32_t* Xs2 = (uint32_t*)smc;
    uint32_t* Th = (uint32_t*)(smc + SM_T);
    float* sbias = (float*)(smc + SM_BIAS);
    int* stok = (int*)(smc + SM_TOK);

    #define STAGE2(lsel) do { \
        const uint4* _w = (const uint4*)(g_Wf + (size_t)((lsel) * 9 + e) * 32768); \
        uint32_t _d = sptr(smc) + SM_B; \
        _Pragma("unroll") \
        for (int _ch = 0; _ch < 2; _ch++) { \
            _Pragma("unroll") \
            for (int _i = 0; _i < 4; _i++) \
                cpa16(_d + _ch * 65536 + (tid + _i * 1024) * 16, \
                      _w + _ch * 4096 + tid + _i * 1024); \
            asm volatile("cp.async.commit_group;"); \
        } \
    } while (0)

    if (tid < MT) stok[tid] = (tid < nr) ? g_tok[e * NTOK + s0 + tid] : -1;
    sbias[tid] = bs[(((tid >> 9) * 4 + ((tid >> 7) & 3)) * 9 + e) * 128 + (tid & 127)];
    STAGE2(0);
    __syncthreads();
    for (int i = tid; i < MT * 32; i += 1024) {
        int r = i >> 5, c4 = i & 31;
        int t = stok[r];
        float4 v = (t >= 0) ? ((const float4*)xin)[(size_t)t * 32 + c4]
                            : make_float4(0.f, 0.f, 0.f, 0.f);
        Xs2[r * 68 + c4 * 2]     = packh2(v.x, v.y);
        Xs2[r * 68 + c4 * 2 + 1] = packh2(v.z, v.w);
    }

    uint32_t arow = sptr(smc) + (uint32_t)((mh2 * 32 + (lane & 7) + ((lane >> 3) & 1) * 8) * 272
                                           + ((lane >> 4) & 1) * 16);

    for (int l = 0; l < 2; l++) {
        float accA[2][2][4], accB[2][2][4];
        #pragma unroll
        for (int mt = 0; mt < 2; mt++)
            #pragma unroll
            for (int nt = 0; nt < 2; nt++)
                #pragma unroll
                for (int j = 0; j < 4; j++) { accA[mt][nt][j] = 0.f; accB[mt][nt][j] = 0.f; }

        #pragma unroll
        for (int ch = 0; ch < 2; ch++) {
            if (ch == 0) asm volatile("cp.async.wait_group 1;");
            else         asm volatile("cp.async.wait_group 0;");
            __syncthreads();
            uint32_t bbA = sptr(smc) + SM_B + ch * 65536 + gA * 4096 + (nq >> 2) * 2048
                           + (nq & 3) * 512 + lane * 16;
            #pragma unroll
            for (int ksq = 0; ksq < 4; ksq++) {
                int ks = ch * 4 + ksq;
                uint32_t a0[4], a1[4];
                ldsm4(a0, arow + ks * 32);
                ldsm4(a1, arow + 16 * 272 + ks * 32);
                uint4 bA = lds128(bbA + ksq * 16384);
                uint4 bB = lds128(bbA + ksq * 16384 + dG);
                mma16(accA[0][0], a0, bA.x, bA.y);
                mma16(accA[0][1], a0, bA.z, bA.w);
                mma16(accA[1][0], a1, bA.x, bA.y);
                mma16(accA[1][1], a1, bA.z, bA.w);
                mma16(accB[0][0], a0, bB.x, bB.y);
                mma16(accB[0][1], a0, bB.z, bB.w);
                mma16(accB[1][0], a1, bB.x, bB.y);
                mma16(accB[1][1], a1, bB.z, bB.w);
            }
        }
        __syncthreads();
        if (l == 0) STAGE2(1);

        const float* sbL = sbias + l * 512;

        #define EPI_LOOP(BODY) \
            _Pragma("unroll") for (int mt = 0; mt < 2; mt++) \
            _Pragma("unroll") for (int nt = 0; nt < 2; nt++) \
            _Pragma("unroll") for (int jh = 0; jh < 2; jh++) { \
                int r = mh2 * 32 + mt * 16 + grp + jh * 8; \
                int cp = nq * 8 + nt * 4 + tig; \
                (void)r; (void)cp; BODY }

        if (gp == 1) {
            EPI_LOOP(
                float t0 = tanha(accA[mt][nt][jh * 2]     + sbL[128 + 2 * cp]);
                float t1 = tanha(accA[mt][nt][jh * 2 + 1] + sbL[128 + 2 * cp + 1]);
                float s0 = sigf(accB[mt][nt][jh * 2]      + sbL[256 + 2 * cp]);
                float s1 = sigf(accB[mt][nt][jh * 2 + 1]  + sbL[256 + 2 * cp + 1]);
                Th[r * 68 + cp] = packh2(t0 * s0, t1 * s1);
            )
        } else {
            EPI_LOOP(
                __half2 xh = u2h(Xs2[r * 68 + cp]);
                accA[mt][nt][jh * 2]     = __low2float(xh)  * sigf(accA[mt][nt][jh * 2]     + sbL[2 * cp]);
                accA[mt][nt][jh * 2 + 1] = __high2float(xh) * sigf(accA[mt][nt][jh * 2 + 1] + sbL[2 * cp + 1]);
                accB[mt][nt][jh * 2]     = sigf(accB[mt][nt][jh * 2]     + sbL[384 + 2 * cp]);
                accB[mt][nt][jh * 2 + 1] = sigf(accB[mt][nt][jh * 2 + 1] + sbL[384 + 2 * cp + 1]);
            )
        }
        __syncthreads();
        if (gp == 0) {
            if (l == 0) {
                EPI_LOOP(
                    __half2 th = u2h(Th[r * 68 + cp]);
                    float o0 = tanha(accA[mt][nt][jh * 2]     + __low2float(th))  * accB[mt][nt][jh * 2];
                    float o1 = tanha(accA[mt][nt][jh * 2 + 1] + __high2float(th)) * accB[mt][nt][jh * 2 + 1];
                    Xs2[r * 68 + cp] = packh2(o0, o1);
                )
            } else {
                EPI_LOOP(
                    __half2 th = u2h(Th[r * 68 + cp]);
                    float o0 = tanha(accA[mt][nt][jh * 2]     + __low2float(th))  * accB[mt][nt][jh * 2];
                    float o1 = tanha(accA[mt][nt][jh * 2 + 1] + __high2float(th)) * accB[mt][nt][jh * 2 + 1];
                    int tk = stok[r];
                    if (tk >= 0)
                        ((float2*)out)[(size_t)tk * 64 + cp] = make_float2(o0, o1);
                )
            }
        }
        #undef EPI_LOOP
    }
    #undef STAGE2
    }
    if (blockIdx.x == 0 && threadIdx.x < 9) g_cnt[threadIdx.x] = 0;
}

extern "C" void kernel_launch(void* const* d_in, const int* in_sizes, int n_in,
                              void* d_out, int out_size) {
    const int* pos = (const int*)d_in[0];
    const float* x = (const float*)d_in[1];
    const float* W = (const float*)d_in[2];
    const float* b = (const float*)d_in[3];
    float* out = (float*)d_out;
    (void)in_sizes; (void)n_in; (void)out_size;
    cudaFuncSetAttribute(k_main, cudaFuncAttributeMaxDynamicSharedMemorySize, SMEM_MAIN);
    k_prep_all<<<416, 512>>>(W, pos);
    k_main<<<MAXTILE, 1024, SMEM_MAIN>>>(x, b, out);
}

// round 16
// speedup vs baseline: 1.1320x; 1.0162x over previous
#include <cuda_runtime.h>
#include <cuda_fp16.h>
#include <cstdint>

#define NTOK 65536
#define MT 64
#define MAXTILE 1040
#define MAXPAIR 520

// byte offsets in dynamic smem
#define SM_X    0         // 128 rows x 272 B (two 64-row planes) = 34816
#define SM_B    34816     // 131072 B (one layer, one expert, both chunks)
#define SM_T    165888    // 64 x 272 B Th plane = 17408
#define SM_BIAS 183296    // 2048 floats (two experts x two layers)
#define SM_TOK  191488    // 128 ints
#define SMEM_MAIN 192000

__device__ int g_cnt[9];
__device__ int g_ntiles;
__device__ unsigned g_done;
__device__ int g_tok[9 * NTOK];
__device__ int g_te[MAXTILE], g_ts[MAXTILE], g_tn[MAXTILE];
// fragment-ordered fp16 weights: per (l,e): 32768 words
__device__ __align__(16) uint32_t g_Wf[18 * 32768];

__device__ __forceinline__ float tanha(float x) {
    float r; asm volatile("tanh.approx.f32 %0,%1;" : "=f"(r) : "f"(x)); return r;
}
__device__ __forceinline__ float sigf(float v) {
    return fmaf(0.5f, tanha(0.5f * v), 0.5f);
}
__device__ __forceinline__ __half2 u2h(uint32_t u) { return *(__half2*)&u; }
__device__ __forceinline__ void mma16(float* c, const uint32_t* a, uint32_t b0, uint32_t b1) {
    asm volatile(
        "mma.sync.aligned.m16n8k16.row.col.f32.f16.f16.f32 "
        "{%0,%1,%2,%3},{%4,%5,%6,%7},{%8,%9},{%0,%1,%2,%3};"
        : "+f"(c[0]), "+f"(c[1]), "+f"(c[2]), "+f"(c[3])
        : "r"(a[0]), "r"(a[1]), "r"(a[2]), "r"(a[3]), "r"(b0), "r"(b1));
}
__device__ __forceinline__ uint32_t sptr(const void* p) {
    return (uint32_t)__cvta_generic_to_shared(p);
}
__device__ __forceinline__ void cpa16(uint32_t dst, const void* src) {
    asm volatile("cp.async.cg.shared.global [%0],[%1],16;" :: "r"(dst), "l"(src));
}
__device__ __forceinline__ uint32_t packh2(float a, float b) {
    __half2 h = __floats2half2_rn(a, b);
    return *(uint32_t*)&h;
}
__device__ __forceinline__ uint4 lds128(uint32_t addr) {
    uint4 v;
    asm volatile("ld.shared.v4.b32 {%0,%1,%2,%3},[%4];"
        : "=r"(v.x), "=r"(v.y), "=r"(v.z), "=r"(v.w) : "r"(addr));
    return v;
}
__device__ __forceinline__ void ldsm4(uint32_t* a, uint32_t addr) {
    asm volatile("ldmatrix.sync.aligned.m8n8.x4.shared.b16 {%0,%1,%2,%3},[%4];"
        : "=r"(a[0]), "=r"(a[1]), "=r"(a[2]), "=r"(a[3]) : "r"(addr));
}

// ---------------- prep: fused wprep (blocks 0..287) + hist/tiles (blocks 288..415) ----
__global__ void k_prep_all(const float* __restrict__ W, const int* __restrict__ pos) {
    int b = blockIdx.x;
    int tid = threadIdx.x;
    if (b < 288) {
        __shared__ float s[32 * 128];
        int m = b >> 2, kg = b & 3;
        int l = m / 36, g = (m / 9) % 4, e = m % 9;
        const float* src = W + (size_t)m * 16384 + kg * 4096;
        for (int i = tid; i < 4096; i += 512) s[i] = src[i];
        __syncthreads();
        uint32_t* dst = g_Wf + (size_t)(l * 9 + e) * 32768 + g * 1024;
        for (int i = tid; i < 2048; i += 512) {
            int ksl = i >> 10, nh = (i >> 9) & 1;
            int ntp = (i >> 7) & 3, lane = (i >> 2) & 31, q = i & 3;
            int tig = lane & 3, grp = lane >> 2, bsel = q & 1;
            int n = nh * 64 + (ntp * 2 + (q >> 1)) * 8 + grp;
            int k0l = ksl * 16 + bsel * 8 + 2 * tig;
            dst[(kg * 2 + ksl) * 4096 + nh * 512 + ntp * 128 + lane * 4 + q] =
                packh2(s[k0l * 128 + n], s[(k0l + 1) * 128 + n]);
        }
    } else {
        __shared__ int scnt[9], sbase[9];
        __shared__ int amlast;
        __shared__ int ts[10];
        int t = (b - 288) * 512 + tid;
        if (tid < 9) scnt[tid] = 0;
        int probe = t & 8191;
        int bad = (pos[2 * probe + 1] != 0);
        bad = __syncthreads_or(bad);
        int p = bad ? pos[t] : pos[2 * t];
        int e = p > 8 ? 8 : (p < 0 ? 0 : p);
        int my = atomicAdd(&scnt[e], 1);
        __syncthreads();
        if (tid < 9) sbase[tid] = atomicAdd(&g_cnt[tid], scnt[tid]);
        __syncthreads();
        g_tok[e * NTOK + sbase[e] + my] = t;
        __threadfence();
        __syncthreads();
        if (tid == 0) amlast = ((atomicAdd(&g_done, 1u) & 127u) == 127u);
        __syncthreads();
        if (amlast) {
            if (tid == 0) {
                ts[0] = 0;
                for (int ee = 0; ee < 9; ee++) ts[ee + 1] = ts[ee] + ((g_cnt[ee] + MT - 1) / MT);
                g_ntiles = ts[9];
            }
            __syncthreads();
            int n = ts[9];
            for (int tt = tid; tt < n; tt += 512) {
                int ee = 0;
                while (!(tt >= ts[ee] && tt < ts[ee + 1])) ee++;
                int s = (tt - ts[ee]) * MT;
                g_te[tt] = ee; g_ts[tt] = s;
                int rem = g_cnt[ee] - s;
                g_tn[tt] = rem < MT ? rem : MT;
            }
        }
    }
}

// ---------------- main: TWO tiles per CTA, both layers, shared B staging ----------------
// warp = (gp in 2, mh2 in 2, nq in 8): m32 x n16 per gate, two gates per warp.
__global__ void __launch_bounds__(1024, 1)
k_main(const float* __restrict__ xin, const float* __restrict__ bs, float* __restrict__ out) {
    extern __shared__ __align__(16) char smc[];
    int pid = blockIdx.x;
    int nt_all = g_ntiles;
    int t0 = pid * 2;
    if (t0 < nt_all) {
    int has1 = (t0 + 1 < nt_all);
    int e0 = g_te[t0];
    int e1 = has1 ? g_te[t0 + 1] : e0;
    int tid = threadIdx.x, lane = tid & 31, w = tid >> 5;
    int gp = w >> 4, mh2 = (w >> 3) & 1, nq = w & 7;
    int tig = lane & 3, grp = lane >> 2;
    int gA = gp ? 1 : 0;
    int dG = gp ? 4096 : 12288;

    uint32_t* Xs2 = (uint32_t*)smc;               // 128 rows x 68 words
    uint32_t* Th = (uint32_t*)(smc + SM_T);       // 64 rows x 68 words
    float* sbias = (float*)(smc + SM_BIAS);       // [st][l][g][c] = 2048 floats
    int* stok = (int*)(smc + SM_TOK);             // 128 ints

    // stage (layer, expert): 128 KB, one commit group
    #define STAGE(lsel, ee) do { \
        const uint4* _w = (const uint4*)(g_Wf + (size_t)((lsel) * 9 + (ee)) * 32768); \
        uint32_t _d = sptr(smc) + SM_B; \
        _Pragma("unroll") \
        for (int _i = 0; _i < 8; _i++) \
            cpa16(_d + (tid + _i * 1024) * 16, _w + tid + _i * 1024); \
        asm volatile("cp.async.commit_group;"); \
    } while (0)

    if (tid < 128) {
        int st = tid >> 6, ix = tid & 63;
        int tt = t0 + st;
        int v = -1;
        if (st == 0 || has1) {
            int ee = st ? e1 : e0;
            if (ix < g_tn[tt]) v = g_tok[ee * NTOK + g_ts[tt] + ix];
        }
        stok[tid] = v;
    }
    for (int i = tid; i < 2048; i += 1024) {
        int st = i >> 10, j = i & 1023;
        int ee = st ? e1 : e0;
        sbias[i] = bs[(((j >> 9) * 4 + ((j >> 7) & 3)) * 9 + ee) * 128 + (j & 127)];
    }
    STAGE(0, e0);              // B stream in flight during X gather
    __syncthreads();
    for (int i = tid; i < 128 * 32; i += 1024) {
        int r = i >> 5, c4 = i & 31;
        int tk = stok[r];
        float4 v = (tk >= 0) ? ((const float4*)xin)[(size_t)tk * 32 + c4]
                             : make_float4(0.f, 0.f, 0.f, 0.f);
        Xs2[r * 68 + c4 * 2]     = packh2(v.x, v.y);
        Xs2[r * 68 + c4 * 2 + 1] = packh2(v.z, v.w);
    }

    uint32_t arow0 = sptr(smc) + (uint32_t)((mh2 * 32 + (lane & 7) + ((lane >> 3) & 1) * 8) * 272
                                            + ((lane >> 4) & 1) * 16);

    for (int l = 0; l < 2; l++) {
        asm volatile("cp.async.wait_group 0;");
        __syncthreads();
        for (int st = 0; st < 2; st++) {
            if (st == 1) {
                if (!has1) { if (l == 0) STAGE(1, e0); break; }
                if (e1 != e0) {        // rare expert-boundary pair: restage
                    STAGE(l, e1);
                    asm volatile("cp.async.wait_group 0;");
                    __syncthreads();
                }
            }
            float accA[2][2][4], accB[2][2][4];
            #pragma unroll
            for (int mt = 0; mt < 2; mt++)
                #pragma unroll
                for (int nt = 0; nt < 2; nt++)
                    #pragma unroll
                    for (int j = 0; j < 4; j++) { accA[mt][nt][j] = 0.f; accB[mt][nt][j] = 0.f; }

            uint32_t ar = arow0 + st * 17408;
            #pragma unroll
            for (int ch = 0; ch < 2; ch++) {
                #pragma unroll
                for (int ksq = 0; ksq < 4; ksq++) {
                    int ks = ch * 4 + ksq;
                    uint32_t a0[4], a1[4];
                    ldsm4(a0, ar + ks * 32);
                    ldsm4(a1, ar + 16 * 272 + ks * 32);
                    uint32_t bbA = sptr(smc) + SM_B + ch * 65536 + ksq * 16384 + gA * 4096
                                   + (nq >> 2) * 2048 + (nq & 3) * 512 + lane * 16;
                    uint4 bA = lds128(bbA);
                    uint4 bB = lds128(bbA + dG);
                    mma16(accA[0][0], a0, bA.x, bA.y);
                    mma16(accA[0][1], a0, bA.z, bA.w);
                    mma16(accA[1][0], a1, bA.x, bA.y);
                    mma16(accA[1][1], a1, bA.z, bA.w);
                    mma16(accB[0][0], a0, bB.x, bB.y);
                    mma16(accB[0][1], a0, bB.z, bB.w);
                    mma16(accB[1][0], a1, bB.x, bB.y);
                    mme16_last:
                    mma16(accB[1][1], a1, bB.z, bB.w);
                }
            }
            __syncthreads();                       // all B reads for this sub-tile done
            if (st == 1 && l == 0) STAGE(1, e0);   // overlap next-layer staging with epilogue

            const float* sbL = sbias + st * 1024 + l * 512;

            #define EPI_LOOP(BODY) \
                _Pragma("unroll") for (int mt = 0; mt < 2; mt++) \
                _Pragma("unroll") for (int nt = 0; nt < 2; nt++) \
                _Pragma("unroll") for (int jh = 0; jh < 2; jh++) { \
                    int rl = mh2 * 32 + mt * 16 + grp + jh * 8; \
                    int r = st * 64 + rl; \
                    int cp = nq * 8 + nt * 4 + tig; \
                    (void)rl; (void)r; (void)cp; BODY }

            if (gp == 1) {
                EPI_LOOP(
                    float tt0 = tanha(accA[mt][nt][jh * 2]     + sbL[128 + 2 * cp]);
                    float tt1 = tanha(accA[mt][nt][jh * 2 + 1] + sbL[128 + 2 * cp + 1]);
                    float s0 = sigf(accB[mt][nt][jh * 2]       + sbL[256 + 2 * cp]);
                    float s1 = sigf(accB[mt][nt][jh * 2 + 1]   + sbL[256 + 2 * cp + 1]);
                    Th[rl * 68 + cp] = packh2(tt0 * s0, tt1 * s1);
                )
            } else {
                EPI_LOOP(
                    __half2 xh = u2h(Xs2[r * 68 + cp]);
                    accA[mt][nt][jh * 2]     = __low2float(xh)  * sigf(accA[mt][nt][jh * 2]     + sbL[2 * cp]);
                    accA[mt][nt][jh * 2 + 1] = __high2float(xh) * sigf(accA[mt][nt][jh * 2 + 1] + sbL[2 * cp + 1]);
                    accB[mt][nt][jh * 2]     = sigf(accB[mt][nt][jh * 2]     + sbL[384 + 2 * cp]);
                    accB[mt][nt][jh * 2 + 1] = sigf(accB[mt][nt][jh * 2 + 1] + sbL[384 + 2 * cp + 1]);
                )
            }
            __syncthreads();
            if (gp == 0) {
                if (l == 0) {
                    EPI_LOOP(
                        __half2 th = u2h(Th[rl * 68 + cp]);
                        float o0 = tanha(accA[mt][nt][jh * 2]     + __low2float(th))  * accB[mt][nt][jh * 2];
                        float o1 = tanha(accA[mt][nt][jh * 2 + 1] + __high2float(th)) * accB[mt][nt][jh * 2 + 1];
                        Xs2[r * 68 + cp] = packh2(o0, o1);
                    )
                } else {
                    EPI_LOOP(
                        __half2 th = u2h(Th[rl * 68 + cp]);
                        float o0 = tanha(accA[mt][nt][jh * 2]     + __low2float(th))  * accB[mt][nt][jh * 2];
                        float o1 = tanha(accA[mt][nt][jh * 2 + 1] + __high2float(th)) * accB[mt][nt][jh * 2 + 1];
                        int tk = stok[r];
                        if (tk >= 0)
                            ((float2*)out)[(size_t)tk * 64 + cp] = make_float2(o0, o1);
                    )
                }
            }
            #undef EPI_LOOP
        }
    }
    #undef STAGE
    }
    // reset histogram for next launch (graph replay)
    if (blockIdx.x == 0 && threadIdx.x < 9) g_cnt[threadIdx.x] = 0;
}

extern "C" void kernel_launch(void* const* d_in, const int* in_sizes, int n_in,
                              void* d_out, int out_size) {
    const int* pos = (const int*)d_in[0];
    const float* x = (const float*)d_in[1];
    const float* W = (const float*)d_in[2];
    const float* b = (const float*)d_in[3];
    float* out = (float*)d_out;
    (void)in_sizes; (void)n_in; (void)out_size;
    cudaFuncSetAttribute(k_main, cudaFuncAttributeMaxDynamicSharedMemorySize, SMEM_MAIN);
    k_prep_all<<<416, 512>>>(W, pos);
    k_main<<<MAXPAIR, 1024, SMEM_MAIN>>>(x, b, out);
}